// round 8
// baseline (speedup 1.0000x reference)
#include <cuda_runtime.h>

// ---------------- shapes ----------------
#define BATCH 128
#define H0 224
#define W0 224
#define PH 56           // pooled H after conv1+maxpool
#define PW 56
#define C1 16
#define C2 32
#define H2 28
#define W2 28
#define N1CNT (128*112*112)
#define N2CNT (128*28*28)
#define NSLOT 64
#define BN_EPS 1e-5f

typedef unsigned long long u64;

// ---------------- scratch ----------------
__device__ float g_mx[(size_t)BATCH * C1 * PH * PW];
__device__ float g_mn[(size_t)BATCH * C1 * PH * PW];
__device__ float g_y2[(size_t)BATCH * C2 * H2 * W2];
__device__ float g_part1[NSLOT][32];
__device__ float g_part2[NSLOT][64];
__device__ float g_bn1s[C1], g_bn1t[C1];
__device__ float g_bn2s[C2], g_bn2t[C2];

// ---------------- packed fp32x2 helpers ----------------
__device__ __forceinline__ void fma2(u64& d, u64 a, u64 b) {
    asm("fma.rn.f32x2 %0, %1, %2, %0;" : "+l"(d) : "l"(a), "l"(b));
}
__device__ __forceinline__ u64 pack_dup(float v) {
    u64 r;
    asm("mov.b64 %0, {%1, %1};" : "=l"(r) : "f"(v));
    return r;
}
__device__ __forceinline__ u64 pack2(float lo, float hi) {
    u64 r;
    asm("mov.b64 %0, {%1, %2};" : "=l"(r) : "f"(lo), "f"(hi));
    return r;
}
__device__ __forceinline__ float2 unpack2(u64 v) {
    float2 f;
    asm("mov.b64 {%0, %1}, %2;" : "=f"(f.x), "=f"(f.y) : "l"(v));
    return f;
}

// ---------------- kernel 0 ----------------
__global__ void zero_kernel() {
    int t = blockIdx.x * blockDim.x + threadIdx.x;
    if (t < NSLOT * 32) ((float*)g_part1)[t] = 0.f;
    if (t < NSLOT * 64) ((float*)g_part2)[t] = 0.f;
}

// ---------------- kernel 1: conv1 + pool min/max + stats (channel-split) ----------------
// 256 threads/block: threads 0-127 compute channels 0-7, threads 128-255
// compute channels 8-15, for 128 pooled pixels per block. Channel group is
// warp-uniform so weight LDS stays broadcast.
__global__ __launch_bounds__(256, 3) void conv1_kernel(
    const float* __restrict__ x, const float* __restrict__ w,
    const float* __restrict__ bias)
{
    __shared__ ulonglong2 ws[27][4];   // [tap][p2] : 2 ch-pairs each
    __shared__ float bs[C1];
    __shared__ float red[8][32];

    int t = threadIdx.x;
    ((float*)red)[t] = 0.f;                       // zero all 256 slots
    for (int i = t; i < 27 * 8; i += 256) {
        int tap = i >> 3, p = i & 7;
        ((u64*)ws)[tap * 8 + p] = pack2(w[(2 * p) * 27 + tap], w[(2 * p + 1) * 27 + tap]);
    }
    if (t < C1) bs[t] = bias[t];
    __syncthreads();

    int g   = t >> 7;                             // channel group: ch 8g..8g+7
    int pix = blockIdx.x * 128 + (t & 127);
    int b   = pix / (PH * PW);
    int rem = pix - b * (PH * PW);
    int pi  = rem / PW;
    int pj  = rem - pi * PW;

    const float* xb = x + (size_t)b * 3 * H0 * W0;

    u64 acc[4][4];
    #pragma unroll
    for (int p = 0; p < 4; p++)
        #pragma unroll
        for (int j = 0; j < 4; j++) acc[p][j] = 0ULL;

    int r0b = 4 * pi - 1;
    int c0b = 4 * pj - 1;

    for (int ic = 0; ic < 3; ic++) {
        const float* xc = xb + (size_t)ic * H0 * W0;
        #pragma unroll
        for (int kh = 0; kh < 3; kh++) {
            int r0 = r0b + kh;
            int r1 = r0 + 2;
            bool r0ok = (unsigned)r0 < (unsigned)H0;
            bool r1ok = (unsigned)r1 < (unsigned)H0;
            float row0[5], row1[5];
            #pragma unroll
            for (int cc = 0; cc < 5; cc++) {
                int c = c0b + cc;
                bool cok = (unsigned)c < (unsigned)W0;
                row0[cc] = (r0ok && cok) ? xc[r0 * W0 + c] : 0.f;
                row1[cc] = (r1ok && cok) ? xc[r1 * W0 + c] : 0.f;
            }
            #pragma unroll
            for (int kw = 0; kw < 3; kw++) {
                u64 v00 = pack_dup(row0[kw]);
                u64 v01 = pack_dup(row0[kw + 2]);
                u64 v10 = pack_dup(row1[kw]);
                u64 v11 = pack_dup(row1[kw + 2]);
                const ulonglong2* wp = &ws[ic * 9 + kh * 3 + kw][2 * g];
                #pragma unroll
                for (int j = 0; j < 2; j++) {
                    ulonglong2 wv = wp[j];
                    fma2(acc[0][2*j],   v00, wv.x); fma2(acc[0][2*j+1], v00, wv.y);
                    fma2(acc[1][2*j],   v01, wv.x); fma2(acc[1][2*j+1], v01, wv.y);
                    fma2(acc[2][2*j],   v10, wv.x); fma2(acc[2][2*j+1], v10, wv.y);
                    fma2(acc[3][2*j],   v11, wv.x); fma2(acc[3][2*j+1], v11, wv.y);
                }
            }
        }
    }

    // epilogue: bias, pool min/max, per-channel stats
    int warp = t >> 5;
    #pragma unroll
    for (int p = 0; p < 4; p++) {
        float2 A0 = unpack2(acc[0][p]);
        float2 A1 = unpack2(acc[1][p]);
        float2 A2 = unpack2(acc[2][p]);
        float2 A3 = unpack2(acc[3][p]);
        #pragma unroll
        for (int h = 0; h < 2; h++) {
            int ch = 8 * g + 2 * p + h;
            float bv = bs[ch];
            float a0 = (h ? A0.y : A0.x) + bv;
            float a1 = (h ? A1.y : A1.x) + bv;
            float a2 = (h ? A2.y : A2.x) + bv;
            float a3 = (h ? A3.y : A3.x) + bv;
            float mx = fmaxf(fmaxf(a0, a1), fmaxf(a2, a3));
            float mn = fminf(fminf(a0, a1), fminf(a2, a3));
            size_t oidx = ((size_t)(b * C1 + ch) * PH + pi) * PW + pj;
            g_mx[oidx] = mx;
            g_mn[oidx] = mn;
            float s = (a0 + a1) + (a2 + a3);
            float q = fmaf(a0, a0, fmaf(a1, a1, fmaf(a2, a2, a3 * a3)));
            #pragma unroll
            for (int off = 16; off; off >>= 1) {
                s += __shfl_xor_sync(0xFFFFFFFFu, s, off);
                q += __shfl_xor_sync(0xFFFFFFFFu, q, off);
            }
            if ((t & 31) == 0) { red[warp][ch] = s; red[warp][16 + ch] = q; }
        }
    }
    __syncthreads();
    if (t < 32) {
        float s = 0.f;
        #pragma unroll
        for (int wv = 0; wv < 8; wv++) s += red[wv][t];
        atomicAdd(&g_part1[blockIdx.x & (NSLOT - 1)][t], s);
    }
}

// ---------------- kernel 2 ----------------
__global__ void bn1_stats_kernel(const float* __restrict__ gam, const float* __restrict__ bet) {
    int t = threadIdx.x;
    if (t < C1) {
        float s = 0.f, q = 0.f;
        for (int w = 0; w < NSLOT; w++) { s += g_part1[w][t]; q += g_part1[w][16 + t]; }
        float inv  = 1.f / (float)N1CNT;
        float mean = s * inv;
        float var  = q * inv - mean * mean;
        float sc   = gam[t] * rsqrtf(var + BN_EPS);
        g_bn1s[t] = sc;
        g_bn1t[t] = bet[t] - mean * sc;
    }
}

// ---------------- kernel 3: conv2 fused BN1+ReLU + stats (channel-split) ----------------
// 128 threads/block: threads 0-63 compute o-channels 0-15, threads 64-127
// compute o-channels 16-31, for 64 pixel-pairs per block.
#define Q2 (W2/2)   // 14
__global__ __launch_bounds__(128, 5) void conv2_kernel(
    const float* __restrict__ w2, const float* __restrict__ b2)
{
    __shared__ u64 pw[C1 * 9][16];
    __shared__ float bs[C2];
    __shared__ float s1s[C1], t1s[C1];
    __shared__ float red[4][64];

    int t = threadIdx.x;
    ((float*)red)[t] = 0.f;
    ((float*)red)[t + 128] = 0.f;
    for (int i = t; i < 144 * 16; i += 128) {
        int tap = i >> 4, p = i & 15;
        pw[tap][p] = pack2(w2[(2 * p) * 144 + tap], w2[(2 * p + 1) * 144 + tap]);
    }
    if (t < C2) bs[t] = b2[t];
    if (t < C1) { s1s[t] = g_bn1s[t]; t1s[t] = g_bn1t[t]; }
    __syncthreads();

    int g   = t >> 6;                 // o-group: o 16g..16g+15
    int pix = blockIdx.x * 64 + (t & 63);
    int b   = pix / (H2 * Q2);
    int rem = pix - b * (H2 * Q2);
    int h2  = rem / Q2;
    int q   = rem - h2 * Q2;

    u64 acc[2][8];
    #pragma unroll
    for (int px = 0; px < 2; px++)
        #pragma unroll
        for (int j = 0; j < 8; j++) acc[px][j] = 0ULL;

    int cb = 4 * q - 1;

    for (int c = 0; c < C1; c++) {
        float sc = s1s[c], tc = t1s[c];
        const float* P = (sc >= 0.f) ? g_mx : g_mn;
        const float* Pb = P + (size_t)(b * C1 + c) * PH * PW;
        #pragma unroll
        for (int kh = 0; kh < 3; kh++) {
            int r = 2 * h2 - 1 + kh;
            bool rok = (unsigned)r < (unsigned)PH;
            float col[5];
            #pragma unroll
            for (int cc = 0; cc < 5; cc++) {
                int cp = cb + cc;
                bool inb = rok && ((unsigned)cp < (unsigned)PW);
                col[cc] = inb ? fmaxf(fmaf(sc, Pb[r * PW + cp], tc), 0.f) : 0.f;
            }
            #pragma unroll
            for (int kw = 0; kw < 3; kw++) {
                u64 v0 = pack_dup(col[kw]);
                u64 v1 = pack_dup(col[kw + 2]);
                const ulonglong2* wp = (const ulonglong2*)&pw[c * 9 + kh * 3 + kw][8 * g];
                #pragma unroll
                for (int j = 0; j < 4; j++) {
                    ulonglong2 wv = wp[j];
                    fma2(acc[0][2*j],   v0, wv.x); fma2(acc[0][2*j+1], v0, wv.y);
                    fma2(acc[1][2*j],   v1, wv.x); fma2(acc[1][2*j+1], v1, wv.y);
                }
            }
        }
    }

    // epilogue: bias, store both pixels, per-channel stats
    int warp = t >> 5;
    #pragma unroll
    for (int p = 0; p < 8; p++) {
        float2 Y0 = unpack2(acc[0][p]);
        float2 Y1 = unpack2(acc[1][p]);
        #pragma unroll
        for (int h = 0; h < 2; h++) {
            int o = 16 * g + 2 * p + h;
            float bv = bs[o];
            float y0 = (h ? Y0.y : Y0.x) + bv;
            float y1 = (h ? Y1.y : Y1.x) + bv;
            size_t base = ((size_t)(b * C2 + o) * H2 + h2) * W2 + 2 * q;
            g_y2[base]     = y0;
            g_y2[base + 1] = y1;
            float s = y0 + y1;
            float qq = fmaf(y0, y0, y1 * y1);
            #pragma unroll
            for (int off = 16; off; off >>= 1) {
                s  += __shfl_xor_sync(0xFFFFFFFFu, s, off);
                qq += __shfl_xor_sync(0xFFFFFFFFu, qq, off);
            }
            if ((t & 31) == 0) { red[warp][o] = s; red[warp][32 + o] = qq; }
        }
    }
    __syncthreads();
    if (t < 64) {
        float s = 0.f;
        #pragma unroll
        for (int wv = 0; wv < 4; wv++) s += red[wv][t];
        atomicAdd(&g_part2[blockIdx.x & (NSLOT - 1)][t], s);
    }
}

// ---------------- kernel 4 ----------------
__global__ void bn2_stats_kernel(const float* __restrict__ gam, const float* __restrict__ bet) {
    int t = threadIdx.x;
    if (t < C2) {
        float s = 0.f, q = 0.f;
        for (int w = 0; w < NSLOT; w++) { s += g_part2[w][t]; q += g_part2[w][32 + t]; }
        float inv  = 1.f / (float)N2CNT;
        float mean = s * inv;
        float var  = q * inv - mean * mean;
        float sc   = gam[t] * rsqrtf(var + BN_EPS);
        g_bn2s[t] = sc;
        g_bn2t[t] = bet[t] - mean * sc;
    }
}

// ---------------- kernel 5: BN2+ReLU + avg + fc + cos ----------------
__global__ __launch_bounds__(256) void final_kernel(
    const float* __restrict__ fcw, const float* __restrict__ fcb,
    float* __restrict__ out)
{
    __shared__ float s2[C2], t2[C2], fw[C2];
    __shared__ float red[8];
    int t = threadIdx.x;
    if (t < C2) {
        s2[t] = g_bn2s[t];
        t2[t] = g_bn2t[t];
        fw[t] = fcw[t] * (1.f / (float)(H2 * W2));
    }
    __syncthreads();

    int b = blockIdx.x;
    const float* Y = g_y2 + (size_t)b * C2 * H2 * W2;
    float a = 0.f;
    for (int idx = t; idx < C2 * H2 * W2; idx += 256) {
        int c = idx / (H2 * W2);
        float v = fmaxf(fmaf(s2[c], Y[idx], t2[c]), 0.f);
        a = fmaf(v, fw[c], a);
    }
    #pragma unroll
    for (int off = 16; off; off >>= 1)
        a += __shfl_xor_sync(0xFFFFFFFFu, a, off);
    if ((t & 31) == 0) red[t >> 5] = a;
    __syncthreads();
    if (t == 0) {
        float tot = 0.f;
        #pragma unroll
        for (int w = 0; w < 8; w++) tot += red[w];
        float logit = tot + fcb[0];
        float p = cosf(logit);
        out[2 * b]     = p;
        out[2 * b + 1] = 1.f - p;
    }
}

// ---------------- launch ----------------
extern "C" void kernel_launch(void* const* d_in, const int* in_sizes, int n_in,
                              void* d_out, int out_size)
{
    const float* x       = (const float*)d_in[0];
    const float* conv1_w = (const float*)d_in[1];
    const float* conv1_b = (const float*)d_in[2];
    const float* bn1_g   = (const float*)d_in[3];
    const float* bn1_b   = (const float*)d_in[4];
    const float* conv2_w = (const float*)d_in[5];
    const float* conv2_b = (const float*)d_in[6];
    const float* bn2_g   = (const float*)d_in[7];
    const float* bn2_b   = (const float*)d_in[8];
    const float* fc_w    = (const float*)d_in[9];
    const float* fc_b    = (const float*)d_in[10];
    float* out = (float*)d_out;

    zero_kernel<<<16, 256>>>();

    // conv1: 2 channel-groups x 401408 pixels, 128 pixels+2 groups per block
    conv1_kernel<<<(BATCH * PH * PW) / 128, 256>>>(x, conv1_w, conv1_b);

    bn1_stats_kernel<<<1, 32>>>(bn1_g, bn1_b);

    // conv2: 2 o-groups x 50176 pixel-pairs, 64 pairs+2 groups per block
    conv2_kernel<<<(BATCH * H2 * Q2) / 64, 128>>>(conv2_w, conv2_b);

    bn2_stats_kernel<<<1, 32>>>(bn2_g, bn2_b);

    final_kernel<<<BATCH, 256>>>(fc_w, fc_b, out);
}

// round 11
// speedup vs baseline: 1.9790x; 1.9790x over previous
#include <cuda_runtime.h>

// ---------------- shapes ----------------
#define BATCH 128
#define H0 224
#define W0 224
#define PH 56           // pooled H after conv1+maxpool
#define PW 56
#define C1 16
#define C2 32
#define H2 28
#define W2 28
#define N1CNT (128*112*112)
#define N2CNT (128*28*28)
#define NSLOT 64
#define BN_EPS 1e-5f

typedef unsigned long long u64;

// ---------------- scratch ----------------
__device__ float g_mx[(size_t)BATCH * C1 * PH * PW];
__device__ float g_mn[(size_t)BATCH * C1 * PH * PW];
__device__ float g_y2[(size_t)BATCH * C2 * H2 * W2];
__device__ float g_part1[NSLOT][32];
__device__ float g_part2[NSLOT][64];
__device__ float g_bn1s[C1], g_bn1t[C1];
__device__ float g_bn2s[C2], g_bn2t[C2];

// ---------------- packed fp32x2 helpers ----------------
__device__ __forceinline__ void fma2(u64& d, u64 a, u64 b) {
    asm("fma.rn.f32x2 %0, %1, %2, %0;" : "+l"(d) : "l"(a), "l"(b));
}
__device__ __forceinline__ u64 pack_dup(float v) {
    u64 r;
    asm("mov.b64 %0, {%1, %1};" : "=l"(r) : "f"(v));
    return r;
}
__device__ __forceinline__ u64 pack2(float lo, float hi) {
    u64 r;
    asm("mov.b64 %0, {%1, %2};" : "=l"(r) : "f"(lo), "f"(hi));
    return r;
}
__device__ __forceinline__ float2 unpack2(u64 v) {
    float2 f;
    asm("mov.b64 {%0, %1}, %2;" : "=f"(f.x), "=f"(f.y) : "l"(v));
    return f;
}

// ---------------- kernel 0 ----------------
__global__ void zero_kernel() {
    int t = blockIdx.x * blockDim.x + threadIdx.x;
    if (t < NSLOT * 32) ((float*)g_part1)[t] = 0.f;
    if (t < NSLOT * 64) ((float*)g_part2)[t] = 0.f;
}

// ---------------- kernel 1: conv1 + pool min/max + stats ----------------
// One thread per pooled pixel, all 16 channels, 4 conv positions.
// Per input channel: load the full 5x5 patch (25 LDG, MLP=25, rows shared
// between the two output rows), then 9 taps of FMA2 — one latency exposure
// per ic instead of three.
__global__ __launch_bounds__(256, 2) void conv1_kernel(
    const float* __restrict__ x, const float* __restrict__ w,
    const float* __restrict__ bias)
{
    __shared__ ulonglong2 ws[27][4];
    __shared__ float bs[C1];
    __shared__ float red[8][32];

    int t = threadIdx.x;
    for (int i = t; i < 27 * 8; i += 256) {
        int tap = i >> 3, p = i & 7;
        ((u64*)ws)[tap * 8 + p] = pack2(w[(2 * p) * 27 + tap], w[(2 * p + 1) * 27 + tap]);
    }
    if (t < C1) bs[t] = bias[t];
    __syncthreads();

    int tid = blockIdx.x * 256 + t;
    int b   = tid / (PH * PW);
    int rem = tid - b * (PH * PW);
    int pi  = rem / PW;
    int pj  = rem - pi * PW;

    const float* xb = x + (size_t)b * 3 * H0 * W0;

    u64 acc[4][8];
    #pragma unroll
    for (int p = 0; p < 4; p++)
        #pragma unroll
        for (int j = 0; j < 8; j++) acc[p][j] = 0ULL;

    int r0b = 4 * pi - 1;
    int c0b = 4 * pj - 1;

    #pragma unroll
    for (int ic = 0; ic < 3; ic++) {
        const float* xc = xb + (size_t)ic * H0 * W0;
        // batched 5x5 patch load
        float row[5][5];
        #pragma unroll
        for (int rr = 0; rr < 5; rr++) {
            int r = r0b + rr;
            bool rok = (unsigned)r < (unsigned)H0;
            #pragma unroll
            for (int cc = 0; cc < 5; cc++) {
                int c = c0b + cc;
                bool cok = (unsigned)c < (unsigned)W0;
                row[rr][cc] = (rok && cok) ? xc[r * W0 + c] : 0.f;
            }
        }
        #pragma unroll
        for (int kh = 0; kh < 3; kh++) {
            #pragma unroll
            for (int kw = 0; kw < 3; kw++) {
                u64 v00 = pack_dup(row[kh][kw]);
                u64 v01 = pack_dup(row[kh][kw + 2]);
                u64 v10 = pack_dup(row[kh + 2][kw]);
                u64 v11 = pack_dup(row[kh + 2][kw + 2]);
                const ulonglong2* wp = ws[ic * 9 + kh * 3 + kw];
                #pragma unroll
                for (int j = 0; j < 4; j++) {
                    ulonglong2 wv = wp[j];
                    fma2(acc[0][2*j],   v00, wv.x); fma2(acc[0][2*j+1], v00, wv.y);
                    fma2(acc[1][2*j],   v01, wv.x); fma2(acc[1][2*j+1], v01, wv.y);
                    fma2(acc[2][2*j],   v10, wv.x); fma2(acc[2][2*j+1], v10, wv.y);
                    fma2(acc[3][2*j],   v11, wv.x); fma2(acc[3][2*j+1], v11, wv.y);
                }
            }
        }
    }

    // epilogue
    int warp = t >> 5;
    #pragma unroll
    for (int p = 0; p < 8; p++) {
        float2 A0 = unpack2(acc[0][p]);
        float2 A1 = unpack2(acc[1][p]);
        float2 A2 = unpack2(acc[2][p]);
        float2 A3 = unpack2(acc[3][p]);
        #pragma unroll
        for (int h = 0; h < 2; h++) {
            int ch = 2 * p + h;
            float bv = bs[ch];
            float a0 = (h ? A0.y : A0.x) + bv;
            float a1 = (h ? A1.y : A1.x) + bv;
            float a2 = (h ? A2.y : A2.x) + bv;
            float a3 = (h ? A3.y : A3.x) + bv;
            float mx = fmaxf(fmaxf(a0, a1), fmaxf(a2, a3));
            float mn = fminf(fminf(a0, a1), fminf(a2, a3));
            size_t oidx = ((size_t)(b * C1 + ch) * PH + pi) * PW + pj;
            g_mx[oidx] = mx;
            g_mn[oidx] = mn;
            float s = (a0 + a1) + (a2 + a3);
            float q = fmaf(a0, a0, fmaf(a1, a1, fmaf(a2, a2, a3 * a3)));
            #pragma unroll
            for (int off = 16; off; off >>= 1) {
                s += __shfl_xor_sync(0xFFFFFFFFu, s, off);
                q += __shfl_xor_sync(0xFFFFFFFFu, q, off);
            }
            if ((t & 31) == 0) { red[warp][ch] = s; red[warp][16 + ch] = q; }
        }
    }
    __syncthreads();
    if (t < 32) {
        float s = 0.f;
        #pragma unroll
        for (int wv = 0; wv < 8; wv++) s += red[wv][t];
        atomicAdd(&g_part1[blockIdx.x & (NSLOT - 1)][t], s);
    }
}

// ---------------- kernel 2 ----------------
__global__ void bn1_stats_kernel(const float* __restrict__ gam, const float* __restrict__ bet) {
    int t = threadIdx.x;
    if (t < C1) {
        float s = 0.f, q = 0.f;
        for (int w = 0; w < NSLOT; w++) { s += g_part1[w][t]; q += g_part1[w][16 + t]; }
        float inv  = 1.f / (float)N1CNT;
        float mean = s * inv;
        float var  = q * inv - mean * mean;
        float sc   = gam[t] * rsqrtf(var + BN_EPS);
        g_bn1s[t] = sc;
        g_bn1t[t] = bet[t] - mean * sc;
    }
}

// ---------------- kernel 3: conv2 fused BN1+ReLU + stats ----------------
// One thread per pair of horizontally adjacent output pixels, all 32 channels.
// Per input channel: load all 15 activated inputs (3 rows x 5 cols, MLP=15),
// and PREFETCH the next channel's 15 into an alternate buffer while computing
// (c-loop unrolled x2 to ping-pong registers without copies).
// Reg cap relaxed to (128,3)=170: kernel is grid-limited, extra regs are free.
#define Q2 (W2/2)   // 14
__global__ __launch_bounds__(128, 3) void conv2_kernel(
    const float* __restrict__ w2, const float* __restrict__ b2)
{
    __shared__ u64 pw[C1 * 9][16];
    __shared__ float bs[C2];
    __shared__ float s1s[C1], t1s[C1];
    __shared__ float red[4][64];

    int t = threadIdx.x;
    for (int i = t; i < 144 * 16; i += 128) {
        int tap = i >> 4, p = i & 15;
        pw[tap][p] = pack2(w2[(2 * p) * 144 + tap], w2[(2 * p + 1) * 144 + tap]);
    }
    if (t < C2) bs[t] = b2[t];
    if (t < C1) { s1s[t] = g_bn1s[t]; t1s[t] = g_bn1t[t]; }
    __syncthreads();

    int tid = blockIdx.x * 128 + t;
    int b   = tid / (H2 * Q2);
    int rem = tid - b * (H2 * Q2);
    int h2  = rem / Q2;
    int q   = rem - h2 * Q2;

    u64 acc[2][16];
    #pragma unroll
    for (int px = 0; px < 2; px++)
        #pragma unroll
        for (int j = 0; j < 16; j++) acc[px][j] = 0ULL;

    int cb = 4 * q - 1;
    int rb = 2 * h2 - 1;

    // load all 15 activated inputs of channel c into buf
    auto load_act = [&](float buf[15], int c) {
        float sc = s1s[c], tc = t1s[c];
        const float* P = (sc >= 0.f) ? g_mx : g_mn;
        const float* Pb = P + (size_t)(b * C1 + c) * PH * PW;
        #pragma unroll
        for (int kh = 0; kh < 3; kh++) {
            int r = rb + kh;
            bool rok = (unsigned)r < (unsigned)PH;
            #pragma unroll
            for (int cc = 0; cc < 5; cc++) {
                int cp = cb + cc;
                bool inb = rok && ((unsigned)cp < (unsigned)PW);
                buf[kh * 5 + cc] = inb ? fmaxf(fmaf(sc, Pb[r * PW + cp], tc), 0.f) : 0.f;
            }
        }
    };

    // compute all 9 taps of channel c from buf
    auto compute = [&](const float buf[15], int c) {
        #pragma unroll
        for (int kh = 0; kh < 3; kh++) {
            #pragma unroll
            for (int kw = 0; kw < 3; kw++) {
                u64 v0 = pack_dup(buf[kh * 5 + kw]);
                u64 v1 = pack_dup(buf[kh * 5 + kw + 2]);
                const ulonglong2* wp = (const ulonglong2*)pw[c * 9 + kh * 3 + kw];
                #pragma unroll
                for (int j = 0; j < 8; j++) {
                    ulonglong2 wv = wp[j];
                    fma2(acc[0][2*j],   v0, wv.x); fma2(acc[0][2*j+1], v0, wv.y);
                    fma2(acc[1][2*j],   v1, wv.x); fma2(acc[1][2*j+1], v1, wv.y);
                }
            }
        }
    };

    float bufA[15], bufB[15];
    load_act(bufA, 0);
    #pragma unroll 1
    for (int c = 0; c < C1; c += 2) {
        load_act(bufB, c + 1);          // prefetch while computing c
        compute(bufA, c);
        if (c + 2 < C1) load_act(bufA, c + 2);  // prefetch while computing c+1
        compute(bufB, c + 1);
    }

    // epilogue
    int warp = t >> 5;
    #pragma unroll
    for (int p = 0; p < 16; p++) {
        float2 Y0 = unpack2(acc[0][p]);
        float2 Y1 = unpack2(acc[1][p]);
        #pragma unroll
        for (int h = 0; h < 2; h++) {
            int o = 2 * p + h;
            float bv = bs[o];
            float y0 = (h ? Y0.y : Y0.x) + bv;
            float y1 = (h ? Y1.y : Y1.x) + bv;
            size_t base = ((size_t)(b * C2 + o) * H2 + h2) * W2 + 2 * q;
            g_y2[base]     = y0;
            g_y2[base + 1] = y1;
            float s = y0 + y1;
            float qq = fmaf(y0, y0, y1 * y1);
            #pragma unroll
            for (int off = 16; off; off >>= 1) {
                s  += __shfl_xor_sync(0xFFFFFFFFu, s, off);
                qq += __shfl_xor_sync(0xFFFFFFFFu, qq, off);
            }
            if ((t & 31) == 0) { red[warp][o] = s; red[warp][32 + o] = qq; }
        }
    }
    __syncthreads();
    if (t < 64) {
        float s = 0.f;
        #pragma unroll
        for (int wv = 0; wv < 4; wv++) s += red[wv][t];
        atomicAdd(&g_part2[blockIdx.x & (NSLOT - 1)][t], s);
    }
}

// ---------------- kernel 4 ----------------
__global__ void bn2_stats_kernel(const float* __restrict__ gam, const float* __restrict__ bet) {
    int t = threadIdx.x;
    if (t < C2) {
        float s = 0.f, q = 0.f;
        for (int w = 0; w < NSLOT; w++) { s += g_part2[w][t]; q += g_part2[w][32 + t]; }
        float inv  = 1.f / (float)N2CNT;
        float mean = s * inv;
        float var  = q * inv - mean * mean;
        float sc   = gam[t] * rsqrtf(var + BN_EPS);
        g_bn2s[t] = sc;
        g_bn2t[t] = bet[t] - mean * sc;
    }
}

// ---------------- kernel 5: BN2+ReLU + avg + fc + cos ----------------
__global__ __launch_bounds__(256) void final_kernel(
    const float* __restrict__ fcw, const float* __restrict__ fcb,
    float* __restrict__ out)
{
    __shared__ float s2[C2], t2[C2], fw[C2];
    __shared__ float red[8];
    int t = threadIdx.x;
    if (t < C2) {
        s2[t] = g_bn2s[t];
        t2[t] = g_bn2t[t];
        fw[t] = fcw[t] * (1.f / (float)(H2 * W2));
    }
    __syncthreads();

    int b = blockIdx.x;
    const float* Y = g_y2 + (size_t)b * C2 * H2 * W2;
    float a = 0.f;
    for (int idx = t; idx < C2 * H2 * W2; idx += 256) {
        int c = idx / (H2 * W2);
        float v = fmaxf(fmaf(s2[c], Y[idx], t2[c]), 0.f);
        a = fmaf(v, fw[c], a);
    }
    #pragma unroll
    for (int off = 16; off; off >>= 1)
        a += __shfl_xor_sync(0xFFFFFFFFu, a, off);
    if ((t & 31) == 0) red[t >> 5] = a;
    __syncthreads();
    if (t == 0) {
        float tot = 0.f;
        #pragma unroll
        for (int w = 0; w < 8; w++) tot += red[w];
        float logit = tot + fcb[0];
        float p = cosf(logit);
        out[2 * b]     = p;
        out[2 * b + 1] = 1.f - p;
    }
}

// ---------------- launch ----------------
extern "C" void kernel_launch(void* const* d_in, const int* in_sizes, int n_in,
                              void* d_out, int out_size)
{
    const float* x       = (const float*)d_in[0];
    const float* conv1_w = (const float*)d_in[1];
    const float* conv1_b = (const float*)d_in[2];
    const float* bn1_g   = (const float*)d_in[3];
    const float* bn1_b   = (const float*)d_in[4];
    const float* conv2_w = (const float*)d_in[5];
    const float* conv2_b = (const float*)d_in[6];
    const float* bn2_g   = (const float*)d_in[7];
    const float* bn2_b   = (const float*)d_in[8];
    const float* fc_w    = (const float*)d_in[9];
    const float* fc_b    = (const float*)d_in[10];
    float* out = (float*)d_out;

    zero_kernel<<<16, 256>>>();

    conv1_kernel<<<(BATCH * PH * PW) / 256, 256>>>(x, conv1_w, conv1_b);

    bn1_stats_kernel<<<1, 32>>>(bn1_g, bn1_b);

    conv2_kernel<<<(BATCH * H2 * Q2) / 128, 128>>>(conv2_w, conv2_b);

    bn2_stats_kernel<<<1, 32>>>(bn2_g, bn2_b);

    final_kernel<<<BATCH, 256>>>(fc_w, fc_b, out);
}